// round 6
// baseline (speedup 1.0000x reference)
#include <cuda_runtime.h>
#include <math.h>

#define HH 30
#define WWG 30
#define HW 900
#define DD 256
#define MAXO 16
#define BB 128
#define FPITCH 288   // 261 feature rows padded to 288 (9 K-tiles of 32)
#define CHUNK 2048
#define HP 20        // hsT pitch (floats), multiple of 4 for aligned LDS.128

// ---------------- device scratch ----------------
__device__ __align__(16) float g_comb[BB * FPITCH * MAXO];  // [b][feat][k]
__device__ __align__(16) float g_u[BB * DD];
__device__ __align__(16) float g_q[BB * DD];
__device__ float g_bdot[BB];
__device__ __align__(16) float g_E[DD * DD];                // W2 @ Wp
__device__ __align__(16) float g_r[DD];                     // b2 @ Wp
__device__ __align__(16) float g_W1p[FPITCH * DD];          // W1 padded
__device__ int   g_valid[BB * MAXO];

// =========================================================================
// Fused pre-kernel (unchanged from round 5; proven).
// =========================================================================
__global__ __launch_bounds__(256) void pre_kernel(const float* __restrict__ grid_emb,
                                                  const int* __restrict__ grid,
                                                  const float* __restrict__ sr,
                                                  const float* __restrict__ W1,
                                                  const float* __restrict__ W2,
                                                  const float* __restrict__ Wp,
                                                  const float* __restrict__ b2) {
    int br = blockIdx.x, tid = threadIdx.x;

    __shared__ int g[HW], lab[HW], slot_of[HW];
    __shared__ unsigned rootbits[32];
    __shared__ int wpre[32];
    __shared__ int s_changed, nvalid;
    __shared__ int robj[MAXO], rmin[MAXO], rmax[MAXO], cmin[MAXO], cmax[MAXO];
    __shared__ int offs[MAXO + 1];
    __shared__ float fpool[4096];
    __shared__ int ipool[CHUNK];

    if (br < BB) {
        int b = br;
        for (int c = tid; c < HW; c += 256) {
            int v = grid[b * HW + c];
            g[c] = v;
            lab[c] = (v > 0) ? c : HW;
            slot_of[c] = -1;
        }
        if (tid < 32) rootbits[tid] = 0;
        __syncthreads();

        for (int it = 0; it < 512; it++) {
            if (tid == 0) s_changed = 0;
            __syncthreads();
            for (int c = tid; c < HW; c += 256) {
                int gc = g[c];
                if (gc > 0) {
                    int m = lab[c];
                    int col = c % WWG;
                    if (c >= WWG && g[c - WWG] == gc) { int t = lab[c - WWG]; if (t < m) m = t; }
                    if (c < HW - WWG && g[c + WWG] == gc) { int t = lab[c + WWG]; if (t < m) m = t; }
                    if (col > 0 && g[c - 1] == gc) { int t = lab[c - 1]; if (t < m) m = t; }
                    if (col < WWG - 1 && g[c + 1] == gc) { int t = lab[c + 1]; if (t < m) m = t; }
                    for (int hop = 0; hop < 32; hop++) {
                        int p = lab[m];
                        if (p >= m) break;
                        m = p;
                    }
                    if (m < lab[c]) { lab[c] = m; s_changed = 1; }
                }
            }
            __syncthreads();
            int ch = s_changed;
            __syncthreads();
            if (!ch) break;
        }

        for (int c = tid; c < HW; c += 256)
            if (g[c] > 0 && lab[c] == c) atomicOr(&rootbits[c >> 5], 1u << (c & 31));
        __syncthreads();
        if (tid == 0) {
            int s = 0;
            for (int w = 0; w < 29; w++) { wpre[w] = s; s += __popc(rootbits[w]); }
            nvalid = s < MAXO ? s : MAXO;
        }
        __syncthreads();
        for (int c = tid; c < HW; c += 256) {
            if (g[c] > 0 && lab[c] == c) {
                int w = c >> 5;
                int rank = wpre[w] + __popc(rootbits[w] & ((1u << (c & 31)) - 1u));
                if (rank < MAXO) { robj[rank] = c; slot_of[c] = rank; }
            }
        }
        if (tid < MAXO) { rmin[tid] = HH; rmax[tid] = -1; cmin[tid] = WWG; cmax[tid] = -1; }
        __syncthreads();
        for (int c = tid; c < HW; c += 256) {
            if (g[c] > 0) {
                int s = slot_of[lab[c]];
                if (s >= 0) {
                    int r = c / WWG, col = c % WWG;
                    atomicMin(&rmin[s], r); atomicMax(&rmax[s], r);
                    atomicMin(&cmin[s], col); atomicMax(&cmax[s], col);
                }
            }
        }
        __syncthreads();

        int nv = nvalid;
        if (tid == 0) {
            int off = 0;
            for (int k = 0; k < nv; k++) {
                offs[k] = off;
                off += (rmax[k] + 1 - rmin[k]) * (cmax[k] + 1 - cmin[k]);
            }
            offs[nv] = off;
        }
        for (int i = tid; i < MAXO * DD; i += 256) fpool[i] = 0.f;
        __syncthreads();

        int total = offs[nv];
        float run = 0.f;
        int prev = -1;
        const float* gbase = grid_emb + (size_t)b * HW * DD + tid;
        for (int base = 0; base < total; base += CHUNK) {
            int n = min(CHUNK, total - base);
            for (int e = tid; e < n; e += 256) {
                int ge = base + e;
                int k = 0;
                while (k + 1 < nv && ge >= offs[k + 1]) k++;
                int local = ge - offs[k];
                int bw = cmax[k] + 1 - cmin[k];
                int li = local / bw, lj = local - li * bw;
                int cell = (rmin[k] + li) * WWG + cmin[k] + lj;
                ipool[e] = (k << 16) | cell;
            }
            __syncthreads();
#pragma unroll 4
            for (int e = 0; e < n; e++) {
                int ent = ipool[e];
                int k = ent >> 16, cell = ent & 0xffff;
                float v = gbase[(size_t)cell * DD];
                if (k != prev) {
                    if (prev >= 0) fpool[prev * DD + tid] += run;
                    run = 0.f;
                    prev = k;
                }
                run += v;
            }
            __syncthreads();
        }
        if (prev >= 0) fpool[prev * DD + tid] += run;
        __syncthreads();

        float* cb = g_comb + (size_t)b * FPITCH * MAXO;
        for (int i = tid; i < FPITCH * MAXO; i += 256) cb[i] = 0.f;
        if (tid < MAXO) g_valid[b * MAXO + tid] = (tid < nv) ? 1 : 0;
        __syncthreads();
        for (int k = 0; k < nv; k++) {
            int y = rmin[k], x = cmin[k];
            int h = rmax[k] + 1 - y, w = cmax[k] + 1 - x;
            cb[tid * MAXO + k] = fpool[k * DD + tid] / (float)(h * w);
            if (tid < 5) {
                float v;
                int color = g[robj[k]];
                if (tid == 0)      v = (float)color * (1.0f / 9.0f);
                else if (tid == 1) v = (float)x * (1.0f / WWG);
                else if (tid == 2) v = (float)y * (1.0f / HH);
                else if (tid == 3) v = (float)w * (1.0f / WWG);
                else               v = (float)h * (1.0f / HH);
                cb[(DD + tid) * MAXO + k] = v;
            }
        }
    } else if (br < 2 * BB) {
        int b = br - BB;
        float* sn = fpool;
        float* sred = fpool + DD;
        const float* base = sr + (size_t)b * 8 * DD + tid;
        float s = 0.f;
#pragma unroll
        for (int j = 0; j < 8; j++) s += base[j * DD];
        s *= 0.125f;
        sred[tid] = s * s; __syncthreads();
        for (int off = 128; off; off >>= 1) { if (tid < off) sred[tid] += sred[tid + off]; __syncthreads(); }
        float nrm = sqrtf(sred[0]);
        __syncthreads();
        float snv = s / fmaxf(nrm, 1e-8f);
        sn[tid] = snv;
        sred[tid] = snv * b2[tid]; __syncthreads();
        for (int off = 128; off; off >>= 1) { if (tid < off) sred[tid] += sred[tid + off]; __syncthreads(); }
        if (tid == 0) g_bdot[b] = sred[0];

        float acc = 0.f;
#pragma unroll 8
        for (int d = 0; d < DD; d++) acc += sn[d] * Wp[d * DD + tid];
        g_q[b * DD + tid] = acc;

        int wid = tid >> 5, lane = tid & 31;
        for (int d = wid; d < DD; d += 8) {
            float a = 0.f;
            const float* wr = W2 + d * DD;
#pragma unroll 4
            for (int e2 = lane; e2 < DD; e2 += 32) a += wr[e2] * sn[e2];
#pragma unroll
            for (int off = 16; off; off >>= 1) a += __shfl_down_sync(0xffffffffu, a, off);
            if (lane == 0) g_u[b * DD + d] = a;
        }
    } else if (br < 2 * BB + 64) {
        int d0 = (br - 2 * BB) * 4, e = tid;
        float* w2s = fpool;
        for (int i = tid; i < 4 * DD; i += 256) w2s[i] = W2[d0 * DD + i];
        __syncthreads();
        float a0 = 0.f, a1 = 0.f, a2 = 0.f, a3 = 0.f;
#pragma unroll 4
        for (int k = 0; k < DD; k++) {
            float wp = Wp[k * DD + e];
            a0 += w2s[0 * DD + k] * wp;
            a1 += w2s[1 * DD + k] * wp;
            a2 += w2s[2 * DD + k] * wp;
            a3 += w2s[3 * DD + k] * wp;
        }
        g_E[(d0 + 0) * DD + e] = a0;
        g_E[(d0 + 1) * DD + e] = a1;
        g_E[(d0 + 2) * DD + e] = a2;
        g_E[(d0 + 3) * DD + e] = a3;
    } else if (br == 2 * BB + 64) {
        float a = 0.f;
#pragma unroll 4
        for (int k = 0; k < DD; k++) a += b2[k] * Wp[k * DD + tid];
        g_r[tid] = a;
    } else {
        int i = (br - (2 * BB + 65)) * 256 + tid;
        const float4* w14 = (const float4*)W1;
        float4 v = make_float4(0.f, 0.f, 0.f, 0.f);
        if (i < 16704) v = w14[i];
        ((float4*)g_W1p)[i] = v;
    }
}
#define PRE_GRID (2 * BB + 65 + 72)   // 393

// =========================================================================
// MLP kernel, 512 threads: each thread 4 rows x 2 cols.
// =========================================================================
__global__ __launch_bounds__(512) void mlp_kernel(const float* __restrict__ b1,
                                                  const float* __restrict__ gamma,
                                                  const float* __restrict__ beta,
                                                  const float* __restrict__ bp,
                                                  const float* __restrict__ osp,
                                                  float* __restrict__ out) {
    int b = blockIdx.x, tid = threadIdx.x;
    int lane = tid & 31, w = tid >> 5;
    int eg = tid & 127, e0 = eg * 2;
    int rg = tid >> 7, r0 = rg * 4;     // rg uniform within a warp

    extern __shared__ float sm[];
    float* csT  = sm;               // 288*16 = 4608
    float* wb0  = csT + 4608;       // 32*256 = 8192
    float* wb1  = wb0 + 8192;       // 8192
    float* hsT  = wb1 + 8192;       // 256*HP = 5120
    float* red  = hsT + 256 * HP;   // 64
    float* red2 = red + 64;         // 64
    float* u_s  = red2 + 64;        // 256
    float* q_s  = u_s + 256;        // 256
    __shared__ float dots[MAXO], mur[MAXO], rstdr[MAXO];
    __shared__ int vld[MAXO];

    const float4* cb4 = (const float4*)(g_comb + (size_t)b * FPITCH * MAXO);
    for (int i = tid; i < (FPITCH * MAXO) / 4; i += 512)
        ((float4*)csT)[i] = cb4[i];
    if (tid < DD) { u_s[tid] = g_u[b * DD + tid]; q_s[tid] = g_q[b * DD + tid]; }
    if (tid < MAXO) vld[tid] = g_valid[b * MAXO + tid];

    const float4* w14 = (const float4*)g_W1p;  // 9 tiles of 2048 float4
    const float4* e4  = (const float4*)g_E;    // 8 tiles of 2048 float4

    // prologue: W1 tile 0 -> wb0 (4 float4 per thread)
    {
        float4 pf[4];
#pragma unroll
        for (int j = 0; j < 4; j++) pf[j] = w14[tid + j * 512];
#pragma unroll
        for (int j = 0; j < 4; j++) ((float4*)wb0)[tid + j * 512] = pf[j];
    }
    __syncthreads();

    float bdot = g_bdot[b];
    float os = osp[0];

    // ---- GEMM1: hidden = gelu(comb @ W1 + b1), 9 tiles of 32 ----
    float acc[4][2];
#pragma unroll
    for (int i = 0; i < 4; i++) { acc[i][0] = 0.f; acc[i][1] = 0.f; }

    for (int t = 0; t < 9; t++) {
        float4 pf[4];
        if (t < 8) {
            int base = (t + 1) * 2048;
#pragma unroll
            for (int j = 0; j < 4; j++) pf[j] = w14[base + tid + j * 512];
        }
        const float* wcur = (t & 1) ? wb1 : wb0;
#pragma unroll
        for (int kk = 0; kk < 32; kk++) {
            float4 c4 = *(const float4*)&csT[(t * 32 + kk) * MAXO + r0];  // broadcast
            float2 w2 = *(const float2*)&wcur[kk * 256 + e0];
            float ca[4] = {c4.x, c4.y, c4.z, c4.w};
#pragma unroll
            for (int i = 0; i < 4; i++) {
                acc[i][0] += ca[i] * w2.x;
                acc[i][1] += ca[i] * w2.y;
            }
        }
        __syncthreads();
        if (t < 8) {
            float* wn = (t & 1) ? wb0 : wb1;
#pragma unroll
            for (int j = 0; j < 4; j++) ((float4*)wn)[tid + j * 512] = pf[j];
            __syncthreads();
        }
    }

    float2 b12 = *(const float2*)&b1[e0];
    float bbv[2] = {b12.x, b12.y};
    float h[4][2];
#pragma unroll
    for (int i = 0; i < 4; i++)
#pragma unroll
        for (int j = 0; j < 2; j++) {
            float xx = acc[i][j] + bbv[j];
            h[i][j] = 0.5f * xx * (1.0f + erff(xx * 0.70710678118654752f));
        }
    // hidden transposed [e][r], pitch HP (aligned float4 stores)
#pragma unroll
    for (int j = 0; j < 2; j++) {
        float4 v = make_float4(h[0][j], h[1][j], h[2][j], h[3][j]);
        *(float4*)&hsT[(e0 + j) * HP + r0] = v;
    }

    // ---- dot[r] = hidden[r].u + bdot ----
    float uu[2] = {u_s[e0], u_s[e0 + 1]};
    float p[4];
#pragma unroll
    for (int i = 0; i < 4; i++) p[i] = h[i][0] * uu[0] + h[i][1] * uu[1];
#pragma unroll
    for (int off = 16; off; off >>= 1)
#pragma unroll
        for (int i = 0; i < 4; i++) p[i] += __shfl_down_sync(0xffffffffu, p[i], off);
    if (lane == 0) {
#pragma unroll
        for (int i = 0; i < 4; i++) red[(r0 + i) * 4 + (w & 3)] = p[i];
    }
    __syncthreads();
    if (tid < MAXO)
        dots[tid] = red[tid * 4] + red[tid * 4 + 1] + red[tid * 4 + 2] + red[tid * 4 + 3] + bdot;

    // GEMM2 prologue: E tile 0 -> wb0
    {
        float4 pf[4];
#pragma unroll
        for (int j = 0; j < 4; j++) pf[j] = e4[tid + j * 512];
#pragma unroll
        for (int j = 0; j < 4; j++) ((float4*)wb0)[tid + j * 512] = pf[j];
    }
    __syncthreads();

    // ---- GEMM2: hE = hidden @ E, 8 tiles of 32 ----
    float a2[4][2];
#pragma unroll
    for (int i = 0; i < 4; i++) { a2[i][0] = 0.f; a2[i][1] = 0.f; }

    for (int t = 0; t < 8; t++) {
        float4 pf[4];
        if (t < 7) {
            int base = (t + 1) * 2048;
#pragma unroll
            for (int j = 0; j < 4; j++) pf[j] = e4[base + tid + j * 512];
        }
        const float* wcur = (t & 1) ? wb1 : wb0;
#pragma unroll
        for (int kk = 0; kk < 32; kk++) {
            float4 h4 = *(const float4*)&hsT[(t * 32 + kk) * HP + r0];  // broadcast
            float2 w2 = *(const float2*)&wcur[kk * 256 + e0];
            float ha[4] = {h4.x, h4.y, h4.z, h4.w};
#pragma unroll
            for (int i = 0; i < 4; i++) {
                a2[i][0] += ha[i] * w2.x;
                a2[i][1] += ha[i] * w2.y;
            }
        }
        __syncthreads();
        if (t < 7) {
            float* wn = (t & 1) ? wb0 : wb1;
#pragma unroll
            for (int j = 0; j < 4; j++) ((float4*)wn)[tid + j * 512] = pf[j];
            __syncthreads();
        }
    }

    // ---- epilogue ----
    float2 bp2 = *(const float2*)&bp[e0];
    float2 rv2 = *(const float2*)&g_r[e0];
    float bpp[2] = {bp2.x, bp2.y};
    float rr[2] = {rv2.x, rv2.y};
    float qq[2] = {q_s[e0], q_s[e0 + 1]};
    float pre[4][2];
#pragma unroll
    for (int i = 0; i < 4; i++) {
        float dt = dots[r0 + i];
        int v = vld[r0 + i];
#pragma unroll
        for (int j = 0; j < 2; j++) {
            float pv = os * (a2[i][j] + rr[j] - dt * qq[j]) + bpp[j];
            pre[i][j] = v ? pv : bpp[j];
        }
    }

    // ---- layernorm ----
    float ps[4], pq[4];
#pragma unroll
    for (int i = 0; i < 4; i++) {
        ps[i] = pre[i][0] + pre[i][1];
        pq[i] = pre[i][0] * pre[i][0] + pre[i][1] * pre[i][1];
    }
#pragma unroll
    for (int off = 16; off; off >>= 1)
#pragma unroll
        for (int i = 0; i < 4; i++) {
            ps[i] += __shfl_down_sync(0xffffffffu, ps[i], off);
            pq[i] += __shfl_down_sync(0xffffffffu, pq[i], off);
        }
    if (lane == 0) {
#pragma unroll
        for (int i = 0; i < 4; i++) {
            red[(r0 + i) * 4 + (w & 3)] = ps[i];
            red2[(r0 + i) * 4 + (w & 3)] = pq[i];
        }
    }
    __syncthreads();
    if (tid < MAXO) {
        float m = (red[tid * 4] + red[tid * 4 + 1] + red[tid * 4 + 2] + red[tid * 4 + 3]) * (1.0f / DD);
        mur[tid] = m;
        float va = (red2[tid * 4] + red2[tid * 4 + 1] + red2[tid * 4 + 2] + red2[tid * 4 + 3]) * (1.0f / DD) - m * m;
        rstdr[tid] = rsqrtf(va + 1e-5f);
    }
    __syncthreads();

    float2 g2 = *(const float2*)&gamma[e0];
    float2 be2 = *(const float2*)&beta[e0];
    float gg[2] = {g2.x, g2.y};
    float bee[2] = {be2.x, be2.y};
#pragma unroll
    for (int i = 0; i < 4; i++) {
        float m = mur[r0 + i], rs = rstdr[r0 + i];
        float2 o;
        o.x = (pre[i][0] - m) * rs * gg[0] + bee[0];
        o.y = (pre[i][1] - m) * rs * gg[1] + bee[1];
        *(float2*)&out[((size_t)(b * MAXO + r0 + i)) * DD + e0] = o;
    }
}

#define MLP_SMEM ((4608 + 8192 + 8192 + 256 * HP + 64 + 64 + 256 + 256) * 4)

// =========================================================================
extern "C" void kernel_launch(void* const* d_in, const int* in_sizes, int n_in,
                              void* d_out, int out_size) {
    const float* grid_emb = (const float*)d_in[0];
    const int*   grid     = (const int*)d_in[1];
    const float* sr       = (const float*)d_in[2];
    const float* W1       = (const float*)d_in[3];
    const float* b1       = (const float*)d_in[4];
    const float* W2       = (const float*)d_in[5];
    const float* b2       = (const float*)d_in[6];
    const float* Wp       = (const float*)d_in[7];
    const float* bp       = (const float*)d_in[8];
    const float* gamma    = (const float*)d_in[9];
    const float* beta     = (const float*)d_in[10];
    const float* os       = (const float*)d_in[11];

    cudaFuncSetAttribute(mlp_kernel, cudaFuncAttributeMaxDynamicSharedMemorySize, MLP_SMEM);

    pre_kernel<<<PRE_GRID, 256>>>(grid_emb, grid, sr, W1, W2, Wp, b2);
    mlp_kernel<<<BB, 512, MLP_SMEM>>>(b1, gamma, beta, bp, os, (float*)d_out);
}

// round 7
// speedup vs baseline: 1.0711x; 1.0711x over previous
#include <cuda_runtime.h>
#include <math.h>

#define HH 30
#define WWG 30
#define HW 900
#define DD 256
#define MAXO 16
#define BB 128
#define FPITCH 288   // 261 feature rows padded to 288 (9 K-tiles of 32)
#define CHUNK 1024

// ---------------- device scratch ----------------
__device__ __align__(16) float g_comb[BB * FPITCH * MAXO];  // [b][feat][k]
__device__ __align__(16) float g_u[BB * DD];
__device__ __align__(16) float g_q[BB * DD];
__device__ float g_bdot[BB];
__device__ __align__(16) float g_E[DD * DD];                // W2 @ Wp
__device__ __align__(16) float g_r[DD];                     // b2 @ Wp
__device__ __align__(16) float g_W1p[FPITCH * DD];          // W1 padded
__device__ int   g_valid[BB * MAXO];

// =========================================================================
// Fused pre-kernel. blockIdx: [0,128) ccl+features, [128,256) prep,
// [256,288) E (8 rows each), 288 r, [289,361) W1 pad copy.
// =========================================================================
__global__ __launch_bounds__(256) void pre_kernel(const float* __restrict__ grid_emb,
                                                  const int* __restrict__ grid,
                                                  const float* __restrict__ sr,
                                                  const float* __restrict__ W1,
                                                  const float* __restrict__ W2,
                                                  const float* __restrict__ Wp,
                                                  const float* __restrict__ b2) {
    int br = blockIdx.x, tid = threadIdx.x;

    __shared__ int g[HW], lab[HW], slot_of[HW];
    __shared__ unsigned rootbits[32];
    __shared__ int wpre[32];
    __shared__ int s_changed, nvalid;
    __shared__ int robj[MAXO], rmin[MAXO], rmax[MAXO], cmin[MAXO], cmax[MAXO];
    __shared__ int offs[MAXO + 1];
    __shared__ float fpool[4096];   // ccl: sacc[16][256] ; prep: sn+red ; E: w2 rows
    __shared__ int ipool[CHUNK];

    if (br < BB) {
        // ---------------- CCL + features ----------------
        int b = br;
        for (int c = tid; c < HW; c += 256) {
            int v = grid[b * HW + c];
            g[c] = v;
            lab[c] = (v > 0) ? c : HW;
            slot_of[c] = -1;
        }
        if (tid < 32) rootbits[tid] = 0;
        __syncthreads();

        for (int it = 0; it < 512; it++) {
            if (tid == 0) s_changed = 0;
            __syncthreads();
            for (int c = tid; c < HW; c += 256) {
                int gc = g[c];
                if (gc > 0) {
                    int m = lab[c];
                    int col = c % WWG;
                    if (c >= WWG && g[c - WWG] == gc) { int t = lab[c - WWG]; if (t < m) m = t; }
                    if (c < HW - WWG && g[c + WWG] == gc) { int t = lab[c + WWG]; if (t < m) m = t; }
                    if (col > 0 && g[c - 1] == gc) { int t = lab[c - 1]; if (t < m) m = t; }
                    if (col < WWG - 1 && g[c + 1] == gc) { int t = lab[c + 1]; if (t < m) m = t; }
                    for (int hop = 0; hop < 32; hop++) {
                        int p = lab[m];
                        if (p >= m) break;
                        m = p;
                    }
                    if (m < lab[c]) { lab[c] = m; s_changed = 1; }
                }
            }
            __syncthreads();
            int ch = s_changed;
            __syncthreads();
            if (!ch) break;
        }

        for (int c = tid; c < HW; c += 256)
            if (g[c] > 0 && lab[c] == c) atomicOr(&rootbits[c >> 5], 1u << (c & 31));
        __syncthreads();
        if (tid == 0) {
            int s = 0;
            for (int w = 0; w < 29; w++) { wpre[w] = s; s += __popc(rootbits[w]); }
            nvalid = s < MAXO ? s : MAXO;
        }
        __syncthreads();
        for (int c = tid; c < HW; c += 256) {
            if (g[c] > 0 && lab[c] == c) {
                int w = c >> 5;
                int rank = wpre[w] + __popc(rootbits[w] & ((1u << (c & 31)) - 1u));
                if (rank < MAXO) { robj[rank] = c; slot_of[c] = rank; }
            }
        }
        if (tid < MAXO) { rmin[tid] = HH; rmax[tid] = -1; cmin[tid] = WWG; cmax[tid] = -1; }
        __syncthreads();
        for (int c = tid; c < HW; c += 256) {
            if (g[c] > 0) {
                int s = slot_of[lab[c]];
                if (s >= 0) {
                    int r = c / WWG, col = c % WWG;
                    atomicMin(&rmin[s], r); atomicMax(&rmax[s], r);
                    atomicMin(&cmin[s], col); atomicMax(&cmax[s], col);
                }
            }
        }
        __syncthreads();

        int nv = nvalid;
        if (tid == 0) {
            int off = 0;
            for (int k = 0; k < nv; k++) {
                offs[k] = off;
                off += (rmax[k] + 1 - rmin[k]) * (cmax[k] + 1 - cmin[k]);
            }
            offs[nv] = off;
        }
        for (int i = tid; i < MAXO * DD; i += 256) fpool[i] = 0.f;
        __syncthreads();

        int total = offs[nv];
        float run = 0.f;
        int prev = -1;
        const float* gbase = grid_emb + (size_t)b * HW * DD + tid;
        for (int base = 0; base < total; base += CHUNK) {
            int n = min(CHUNK, total - base);
            for (int e = tid; e < n; e += 256) {
                int ge = base + e;
                int k = 0;
                while (k + 1 < nv && ge >= offs[k + 1]) k++;
                int local = ge - offs[k];
                int bw = cmax[k] + 1 - cmin[k];
                int li = local / bw, lj = local - li * bw;
                int cell = (rmin[k] + li) * WWG + cmin[k] + lj;
                ipool[e] = (k << 16) | cell;
            }
            __syncthreads();
#pragma unroll 4
            for (int e = 0; e < n; e++) {
                int ent = ipool[e];
                int k = ent >> 16, cell = ent & 0xffff;
                float v = gbase[(size_t)cell * DD];
                if (k != prev) {
                    if (prev >= 0) fpool[prev * DD + tid] += run;
                    run = 0.f;
                    prev = k;
                }
                run += v;
            }
            __syncthreads();
        }
        if (prev >= 0) fpool[prev * DD + tid] += run;
        __syncthreads();

        float* cb = g_comb + (size_t)b * FPITCH * MAXO;
        for (int i = tid; i < FPITCH * MAXO; i += 256) cb[i] = 0.f;
        if (tid < MAXO) g_valid[b * MAXO + tid] = (tid < nv) ? 1 : 0;
        __syncthreads();
        for (int k = 0; k < nv; k++) {
            int y = rmin[k], x = cmin[k];
            int h = rmax[k] + 1 - y, w = cmax[k] + 1 - x;
            cb[tid * MAXO + k] = fpool[k * DD + tid] / (float)(h * w);
            if (tid < 5) {
                float v;
                int color = g[robj[k]];
                if (tid == 0)      v = (float)color * (1.0f / 9.0f);
                else if (tid == 1) v = (float)x * (1.0f / WWG);
                else if (tid == 2) v = (float)y * (1.0f / HH);
                else if (tid == 3) v = (float)w * (1.0f / WWG);
                else               v = (float)h * (1.0f / HH);
                cb[(DD + tid) * MAXO + k] = v;
            }
        }
    } else if (br < 2 * BB) {
        // ---------------- prep: sn, u, q, bdot ----------------
        int b = br - BB;
        float* sn = fpool;
        float* sred = fpool + DD;
        const float* base = sr + (size_t)b * 8 * DD + tid;
        float s = 0.f;
#pragma unroll
        for (int j = 0; j < 8; j++) s += base[j * DD];
        s *= 0.125f;
        sred[tid] = s * s; __syncthreads();
        for (int off = 128; off; off >>= 1) { if (tid < off) sred[tid] += sred[tid + off]; __syncthreads(); }
        float nrm = sqrtf(sred[0]);
        __syncthreads();
        float snv = s / fmaxf(nrm, 1e-8f);
        sn[tid] = snv;
        sred[tid] = snv * b2[tid]; __syncthreads();
        for (int off = 128; off; off >>= 1) { if (tid < off) sred[tid] += sred[tid + off]; __syncthreads(); }
        if (tid == 0) g_bdot[b] = sred[0];

        float acc = 0.f;
#pragma unroll 8
        for (int d = 0; d < DD; d++) acc += sn[d] * Wp[d * DD + tid];
        g_q[b * DD + tid] = acc;

        int wid = tid >> 5, lane = tid & 31;
        for (int d = wid; d < DD; d += 8) {
            float a = 0.f;
            const float* wr = W2 + d * DD;
#pragma unroll 4
            for (int e2 = lane; e2 < DD; e2 += 32) a += wr[e2] * sn[e2];
#pragma unroll
            for (int off = 16; off; off >>= 1) a += __shfl_down_sync(0xffffffffu, a, off);
            if (lane == 0) g_u[b * DD + d] = a;
        }
    } else if (br < 2 * BB + 32) {
        // ---------------- E = W2 @ Wp, 8 rows/block, k-unroll 8 ----------------
        int d0 = (br - 2 * BB) * 8, e = tid;
        float* w2s = fpool;   // 8*256
        for (int i = tid; i < 8 * DD; i += 256) w2s[i] = W2[d0 * DD + i];
        __syncthreads();
        float a[8];
#pragma unroll
        for (int r = 0; r < 8; r++) a[r] = 0.f;
        for (int k = 0; k < DD; k += 8) {
            float wp[8];
#pragma unroll
            for (int j = 0; j < 8; j++) wp[j] = Wp[(k + j) * DD + e];
#pragma unroll
            for (int j = 0; j < 8; j++)
#pragma unroll
                for (int r = 0; r < 8; r++) a[r] += w2s[r * DD + k + j] * wp[j];
        }
#pragma unroll
        for (int r = 0; r < 8; r++) g_E[(d0 + r) * DD + e] = a[r];
    } else if (br == 2 * BB + 32) {
        // ---------------- r = b2 @ Wp ----------------
        float a = 0.f;
#pragma unroll 8
        for (int k = 0; k < DD; k++) a += b2[k] * Wp[k * DD + tid];
        g_r[tid] = a;
    } else {
        // ---------------- pad W1 (261x256) -> g_W1p (288x256) ----------------
        int i = (br - (2 * BB + 33)) * 256 + tid;   // float4 idx 0..18431
        const float4* w14 = (const float4*)W1;      // 16704 real float4s
        float4 v = make_float4(0.f, 0.f, 0.f, 0.f);
        if (i < 16704) v = w14[i];
        ((float4*)g_W1p)[i] = v;
    }
}
#define PRE_GRID (2 * BB + 33 + 72)   // 361

// =========================================================================
// MLP kernel — EXACT round-4 version (measured 32.5us, FFMA-pipe floor).
// =========================================================================
__global__ __launch_bounds__(256) void mlp_kernel(const float* __restrict__ b1,
                                                  const float* __restrict__ gamma,
                                                  const float* __restrict__ beta,
                                                  const float* __restrict__ bp,
                                                  const float* __restrict__ osp,
                                                  float* __restrict__ out) {
    int b = blockIdx.x, tid = threadIdx.x;
    int rg = tid >> 6, cg = tid & 63;
    int r0 = rg * 4, e0 = cg * 4;
    int wid = tid >> 5, lane = tid & 31;

    extern __shared__ float sm[];
    float* csT  = sm;               // 288*16 = 4608
    float* wb0  = csT + 4608;       // 32*256 = 8192
    float* wb1  = wb0 + 8192;       // 8192
    float* hsT  = wb1 + 8192;       // 256*16 = 4096
    float* red  = hsT + 4096;       // 32
    float* red2 = red + 32;         // 32
    float* u_s  = red2 + 32;        // 256
    float* q_s  = u_s + 256;        // 256
    __shared__ float dots[MAXO], mur[MAXO], rstdr[MAXO];
    __shared__ int vld[MAXO];

    const float4* cb4 = (const float4*)(g_comb + (size_t)b * FPITCH * MAXO);
    for (int i = tid; i < (FPITCH * MAXO) / 4; i += 256)
        ((float4*)csT)[i] = cb4[i];
    u_s[tid] = g_u[b * DD + tid];
    q_s[tid] = g_q[b * DD + tid];
    if (tid < MAXO) vld[tid] = g_valid[b * MAXO + tid];

    const float4* w14 = (const float4*)g_W1p;  // 9 tiles of 2048 float4
    const float4* e4  = (const float4*)g_E;    // 8 tiles of 2048 float4

    {
        float4 pf[8];
#pragma unroll
        for (int j = 0; j < 8; j++) pf[j] = w14[tid + j * 256];
#pragma unroll
        for (int j = 0; j < 8; j++) ((float4*)wb0)[tid + j * 256] = pf[j];
    }
    __syncthreads();

    float bdot = g_bdot[b];
    float os = osp[0];

    float acc[4][4];
#pragma unroll
    for (int i = 0; i < 4; i++)
#pragma unroll
        for (int j = 0; j < 4; j++) acc[i][j] = 0.f;

    for (int t = 0; t < 9; t++) {
        float4 pf[8];
        if (t < 8) {
            int base = (t + 1) * 2048;
#pragma unroll
            for (int j = 0; j < 8; j++) pf[j] = w14[base + tid + j * 256];
        }
        const float* wcur = (t & 1) ? wb1 : wb0;
#pragma unroll
        for (int kk = 0; kk < 32; kk++) {
            float4 c4 = *(const float4*)&csT[(t * 32 + kk) * MAXO + r0];
            float4 w4 = *(const float4*)&wcur[kk * 256 + e0];
            float ca[4] = {c4.x, c4.y, c4.z, c4.w};
            float wa[4] = {w4.x, w4.y, w4.z, w4.w};
#pragma unroll
            for (int i = 0; i < 4; i++)
#pragma unroll
                for (int j = 0; j < 4; j++) acc[i][j] += ca[i] * wa[j];
        }
        __syncthreads();
        if (t < 8) {
            float* wn = (t & 1) ? wb0 : wb1;
#pragma unroll
            for (int j = 0; j < 8; j++) ((float4*)wn)[tid + j * 256] = pf[j];
            __syncthreads();
        }
    }

    float4 b14 = *(const float4*)&b1[e0];
    float bb[4] = {b14.x, b14.y, b14.z, b14.w};
    float h[4][4];
#pragma unroll
    for (int i = 0; i < 4; i++)
#pragma unroll
        for (int j = 0; j < 4; j++) {
            float xx = acc[i][j] + bb[j];
            h[i][j] = 0.5f * xx * (1.0f + erff(xx * 0.70710678118654752f));
        }
#pragma unroll
    for (int j = 0; j < 4; j++) {
        float4 v = make_float4(h[0][j], h[1][j], h[2][j], h[3][j]);
        *(float4*)&hsT[(e0 + j) * MAXO + r0] = v;
    }

    float uu[4] = {u_s[e0], u_s[e0 + 1], u_s[e0 + 2], u_s[e0 + 3]};
    float p[4];
#pragma unroll
    for (int i = 0; i < 4; i++)
        p[i] = h[i][0] * uu[0] + h[i][1] * uu[1] + h[i][2] * uu[2] + h[i][3] * uu[3];
#pragma unroll
    for (int off = 16; off; off >>= 1)
#pragma unroll
        for (int i = 0; i < 4; i++) p[i] += __shfl_down_sync(0xffffffffu, p[i], off);
    if (lane == 0) {
#pragma unroll
        for (int i = 0; i < 4; i++) red[(r0 + i) * 2 + (wid & 1)] = p[i];
    }
    __syncthreads();
    if (tid < MAXO) dots[tid] = red[tid * 2] + red[tid * 2 + 1] + bdot;

    {
        float4 pf[8];
#pragma unroll
        for (int j = 0; j < 8; j++) pf[j] = e4[tid + j * 256];
#pragma unroll
        for (int j = 0; j < 8; j++) ((float4*)wb0)[tid + j * 256] = pf[j];
    }
    __syncthreads();

    float a2[4][4];
#pragma unroll
    for (int i = 0; i < 4; i++)
#pragma unroll
        for (int j = 0; j < 4; j++) a2[i][j] = 0.f;

    for (int t = 0; t < 8; t++) {
        float4 pf[8];
        if (t < 7) {
            int base = (t + 1) * 2048;
#pragma unroll
            for (int j = 0; j < 8; j++) pf[j] = e4[base + tid + j * 256];
        }
        const float* wcur = (t & 1) ? wb1 : wb0;
#pragma unroll
        for (int kk = 0; kk < 32; kk++) {
            float4 h4 = *(const float4*)&hsT[(t * 32 + kk) * MAXO + r0];
            float4 w4 = *(const float4*)&wcur[kk * 256 + e0];
            float ha[4] = {h4.x, h4.y, h4.z, h4.w};
            float wa[4] = {w4.x, w4.y, w4.z, w4.w};
#pragma unroll
            for (int i = 0; i < 4; i++)
#pragma unroll
                for (int j = 0; j < 4; j++) a2[i][j] += ha[i] * wa[j];
        }
        __syncthreads();
        if (t < 7) {
            float* wn = (t & 1) ? wb0 : wb1;
#pragma unroll
            for (int j = 0; j < 8; j++) ((float4*)wn)[tid + j * 256] = pf[j];
            __syncthreads();
        }
    }

    float4 bp4 = *(const float4*)&bp[e0];
    float4 rv4 = *(const float4*)&g_r[e0];
    float bpp[4] = {bp4.x, bp4.y, bp4.z, bp4.w};
    float rr[4] = {rv4.x, rv4.y, rv4.z, rv4.w};
    float qq[4] = {q_s[e0], q_s[e0 + 1], q_s[e0 + 2], q_s[e0 + 3]};
    float pre[4][4];
#pragma unroll
    for (int i = 0; i < 4; i++) {
        float dt = dots[r0 + i];
        int v = vld[r0 + i];
#pragma unroll
        for (int j = 0; j < 4; j++) {
            float pv = os * (a2[i][j] + rr[j] - dt * qq[j]) + bpp[j];
            pre[i][j] = v ? pv : bpp[j];
        }
    }

    float ps[4], pq[4];
#pragma unroll
    for (int i = 0; i < 4; i++) {
        ps[i] = pre[i][0] + pre[i][1] + pre[i][2] + pre[i][3];
        pq[i] = pre[i][0] * pre[i][0] + pre[i][1] * pre[i][1] +
                pre[i][2] * pre[i][2] + pre[i][3] * pre[i][3];
    }
#pragma unroll
    for (int off = 16; off; off >>= 1)
#pragma unroll
        for (int i = 0; i < 4; i++) {
            ps[i] += __shfl_down_sync(0xffffffffu, ps[i], off);
            pq[i] += __shfl_down_sync(0xffffffffu, pq[i], off);
        }
    if (lane == 0) {
#pragma unroll
        for (int i = 0; i < 4; i++) {
            red[(r0 + i) * 2 + (wid & 1)] = ps[i];
            red2[(r0 + i) * 2 + (wid & 1)] = pq[i];
        }
    }
    __syncthreads();
    if (tid < MAXO) {
        float m = (red[tid * 2] + red[tid * 2 + 1]) * (1.0f / DD);
        mur[tid] = m;
        float va = (red2[tid * 2] + red2[tid * 2 + 1]) * (1.0f / DD) - m * m;
        rstdr[tid] = rsqrtf(va + 1e-5f);
    }
    __syncthreads();

    float4 g4 = *(const float4*)&gamma[e0];
    float4 be4 = *(const float4*)&beta[e0];
    float gg[4] = {g4.x, g4.y, g4.z, g4.w};
    float bee[4] = {be4.x, be4.y, be4.z, be4.w};
#pragma unroll
    for (int i = 0; i < 4; i++) {
        float m = mur[r0 + i], rs = rstdr[r0 + i];
        float4 o;
        o.x = (pre[i][0] - m) * rs * gg[0] + bee[0];
        o.y = (pre[i][1] - m) * rs * gg[1] + bee[1];
        o.z = (pre[i][2] - m) * rs * gg[2] + bee[2];
        o.w = (pre[i][3] - m) * rs * gg[3] + bee[3];
        *(float4*)&out[((size_t)(b * MAXO + r0 + i)) * DD + e0] = o;
    }
}

#define MLP_SMEM ((4608 + 8192 + 8192 + 4096 + 32 + 32 + 256 + 256) * 4)

// =========================================================================
extern "C" void kernel_launch(void* const* d_in, const int* in_sizes, int n_in,
                              void* d_out, int out_size) {
    const float* grid_emb = (const float*)d_in[0];
    const int*   grid     = (const int*)d_in[1];
    const float* sr       = (const float*)d_in[2];
    const float* W1       = (const float*)d_in[3];
    const float* b1       = (const float*)d_in[4];
    const float* W2       = (const float*)d_in[5];
    const float* b2       = (const float*)d_in[6];
    const float* Wp       = (const float*)d_in[7];
    const float* bp       = (const float*)d_in[8];
    const float* gamma    = (const float*)d_in[9];
    const float* beta     = (const float*)d_in[10];
    const float* os       = (const float*)d_in[11];

    cudaFuncSetAttribute(mlp_kernel, cudaFuncAttributeMaxDynamicSharedMemorySize, MLP_SMEM);

    pre_kernel<<<PRE_GRID, 256>>>(grid_emb, grid, sr, W1, W2, Wp, b2);
    mlp_kernel<<<BB, 256, MLP_SMEM>>>(b1, gamma, beta, bp, os, (float*)d_out);
}

// round 8
// speedup vs baseline: 1.0934x; 1.0208x over previous
#include <cuda_runtime.h>
#include <math.h>

#define HH 30
#define WWG 30
#define HW 900
#define DD 256
#define MAXO 16
#define BB 128
#define FPITCH 288   // 261 feature rows padded to 288 (9 K-tiles of 32)
#define CHUNK 1024
#define PF 16        // pooling prefetch depth

// ---------------- device scratch ----------------
__device__ __align__(16) float g_comb[BB * FPITCH * MAXO];  // [b][feat][k]
__device__ __align__(16) float g_u[BB * DD];
__device__ __align__(16) float g_q[BB * DD];
__device__ float g_bdot[BB];
__device__ __align__(16) float g_E[DD * DD];                // W2 @ Wp
__device__ __align__(16) float g_r[DD];                     // b2 @ Wp
__device__ __align__(16) float g_W1p[FPITCH * DD];          // W1 padded
__device__ int   g_valid[BB * MAXO];

// =========================================================================
// Fused pre-kernel. blockIdx: [0,128) ccl+features, [128,256) prep,
// [256,288) E (8 rows each), 288 r, [289,361) W1 pad copy.
// =========================================================================
__global__ __launch_bounds__(256) void pre_kernel(const float* __restrict__ grid_emb,
                                                  const int* __restrict__ grid,
                                                  const float* __restrict__ sr,
                                                  const float* __restrict__ W1,
                                                  const float* __restrict__ W2,
                                                  const float* __restrict__ Wp,
                                                  const float* __restrict__ b2) {
    int br = blockIdx.x, tid = threadIdx.x;

    __shared__ int g[HW], lab[HW], slot_of[HW];
    __shared__ unsigned rootbits[32];
    __shared__ int wpre[32];
    __shared__ int s_flag[2];
    __shared__ int nvalid;
    __shared__ int robj[MAXO], rmin[MAXO], rmax[MAXO], cmin[MAXO], cmax[MAXO];
    __shared__ int offs[MAXO + 1];
    __shared__ float fpool[4096];   // ccl: sacc[16][256] ; prep: sn+red ; E: w2 rows
    __shared__ int ipool[CHUNK];

    if (br < BB) {
        // ---------------- CCL + features ----------------
        int b = br;
        for (int c = tid; c < HW; c += 256) {
            int v = grid[b * HW + c];
            g[c] = v;
            lab[c] = (v > 0) ? c : HW;
            slot_of[c] = -1;
        }
        if (tid < 32) rootbits[tid] = 0;
        if (tid == 0) { s_flag[0] = 0; s_flag[1] = 0; }
        __syncthreads();

        // label propagation, 2 syncs/iteration (double-buffered change flag)
        for (int it = 0; it < 512; it++) {
            int f = it & 1;
            if (tid == 0) s_flag[1 - f] = 0;   // prepare next iter's flag
            int changed = 0;
            for (int c = tid; c < HW; c += 256) {
                int gc = g[c];
                if (gc > 0) {
                    int m = lab[c];
                    int col = c % WWG;
                    if (c >= WWG && g[c - WWG] == gc) { int t = lab[c - WWG]; if (t < m) m = t; }
                    if (c < HW - WWG && g[c + WWG] == gc) { int t = lab[c + WWG]; if (t < m) m = t; }
                    if (col > 0 && g[c - 1] == gc) { int t = lab[c - 1]; if (t < m) m = t; }
                    if (col < WWG - 1 && g[c + 1] == gc) { int t = lab[c + 1]; if (t < m) m = t; }
#pragma unroll
                    for (int hop = 0; hop < 8; hop++) {
                        int p = lab[m];
                        if (p >= m) break;
                        m = p;
                    }
                    if (m < lab[c]) { lab[c] = m; changed = 1; }
                }
            }
            if (changed) s_flag[f] = 1;
            __syncthreads();
            int ch = s_flag[f];
            __syncthreads();
            if (!ch) break;
        }

        for (int c = tid; c < HW; c += 256)
            if (g[c] > 0 && lab[c] == c) atomicOr(&rootbits[c >> 5], 1u << (c & 31));
        __syncthreads();
        if (tid == 0) {
            int s = 0;
            for (int w = 0; w < 29; w++) { wpre[w] = s; s += __popc(rootbits[w]); }
            nvalid = s < MAXO ? s : MAXO;
        }
        __syncthreads();
        for (int c = tid; c < HW; c += 256) {
            if (g[c] > 0 && lab[c] == c) {
                int w = c >> 5;
                int rank = wpre[w] + __popc(rootbits[w] & ((1u << (c & 31)) - 1u));
                if (rank < MAXO) { robj[rank] = c; slot_of[c] = rank; }
            }
        }
        if (tid < MAXO) { rmin[tid] = HH; rmax[tid] = -1; cmin[tid] = WWG; cmax[tid] = -1; }
        __syncthreads();
        for (int c = tid; c < HW; c += 256) {
            if (g[c] > 0) {
                int s = slot_of[lab[c]];
                if (s >= 0) {
                    int r = c / WWG, col = c % WWG;
                    atomicMin(&rmin[s], r); atomicMax(&rmax[s], r);
                    atomicMin(&cmin[s], col); atomicMax(&cmax[s], col);
                }
            }
        }
        __syncthreads();

        int nv = nvalid;
        if (tid == 0) {
            int off = 0;
            for (int k = 0; k < nv; k++) {
                offs[k] = off;
                off += (rmax[k] + 1 - rmin[k]) * (cmax[k] + 1 - cmin[k]);
            }
            offs[nv] = off;
        }
        for (int i = tid; i < MAXO * DD; i += 256) fpool[i] = 0.f;
        __syncthreads();

        int total = offs[nv];
        float run = 0.f;
        int prev = -1;
        const float* gbase = grid_emb + (size_t)b * HW * DD + tid;
        for (int base = 0; base < total; base += CHUNK) {
            int n = min(CHUNK, total - base);
            for (int e = tid; e < n; e += 256) {
                int ge = base + e;
                int k = 0;
                while (k + 1 < nv && ge >= offs[k + 1]) k++;
                int local = ge - offs[k];
                int bw = cmax[k] + 1 - cmin[k];
                int li = local / bw, lj = local - li * bw;
                int cell = (rmin[k] + li) * WWG + cmin[k] + lj;
                ipool[e] = (k << 16) | cell;
            }
            __syncthreads();
            // prefetch-16 accumulate: 16 independent LDGs in flight
            for (int e0b = 0; e0b < n; e0b += PF) {
                int m = n - e0b; if (m > PF) m = PF;
                float v[PF]; int kk[PF];
#pragma unroll
                for (int j = 0; j < PF; j++) {
                    if (j < m) {
                        int ent = ipool[e0b + j];
                        kk[j] = ent >> 16;
                        v[j] = gbase[(size_t)(ent & 0xffff) * DD];
                    }
                }
#pragma unroll
                for (int j = 0; j < PF; j++) {
                    if (j < m) {
                        if (kk[j] != prev) {
                            if (prev >= 0) fpool[prev * DD + tid] += run;
                            run = 0.f;
                            prev = kk[j];
                        }
                        run += v[j];
                    }
                }
            }
            __syncthreads();
        }
        if (prev >= 0) fpool[prev * DD + tid] += run;
        __syncthreads();

        float* cb = g_comb + (size_t)b * FPITCH * MAXO;
        for (int i = tid; i < FPITCH * MAXO; i += 256) cb[i] = 0.f;
        if (tid < MAXO) g_valid[b * MAXO + tid] = (tid < nv) ? 1 : 0;
        __syncthreads();
        for (int k = 0; k < nv; k++) {
            int y = rmin[k], x = cmin[k];
            int h = rmax[k] + 1 - y, w = cmax[k] + 1 - x;
            cb[tid * MAXO + k] = fpool[k * DD + tid] / (float)(h * w);
            if (tid < 5) {
                float v;
                int color = g[robj[k]];
                if (tid == 0)      v = (float)color * (1.0f / 9.0f);
                else if (tid == 1) v = (float)x * (1.0f / WWG);
                else if (tid == 2) v = (float)y * (1.0f / HH);
                else if (tid == 3) v = (float)w * (1.0f / WWG);
                else               v = (float)h * (1.0f / HH);
                cb[(DD + tid) * MAXO + k] = v;
            }
        }
    } else if (br < 2 * BB) {
        // ---------------- prep: sn, u, q, bdot ----------------
        int b = br - BB;
        float* sn = fpool;
        float* sred = fpool + DD;
        const float* base = sr + (size_t)b * 8 * DD + tid;
        float s = 0.f;
#pragma unroll
        for (int j = 0; j < 8; j++) s += base[j * DD];
        s *= 0.125f;
        sred[tid] = s * s; __syncthreads();
        for (int off = 128; off; off >>= 1) { if (tid < off) sred[tid] += sred[tid + off]; __syncthreads(); }
        float nrm = sqrtf(sred[0]);
        __syncthreads();
        float snv = s / fmaxf(nrm, 1e-8f);
        sn[tid] = snv;
        sred[tid] = snv * b2[tid]; __syncthreads();
        for (int off = 128; off; off >>= 1) { if (tid < off) sred[tid] += sred[tid + off]; __syncthreads(); }
        if (tid == 0) g_bdot[b] = sred[0];

        float acc = 0.f;
#pragma unroll 8
        for (int d = 0; d < DD; d++) acc += sn[d] * Wp[d * DD + tid];
        g_q[b * DD + tid] = acc;

        int wid = tid >> 5, lane = tid & 31;
        for (int d = wid; d < DD; d += 8) {
            float a = 0.f;
            const float* wr = W2 + d * DD;
#pragma unroll 4
            for (int e2 = lane; e2 < DD; e2 += 32) a += wr[e2] * sn[e2];
#pragma unroll
            for (int off = 16; off; off >>= 1) a += __shfl_down_sync(0xffffffffu, a, off);
            if (lane == 0) g_u[b * DD + d] = a;
        }
    } else if (br < 2 * BB + 32) {
        // ---------------- E = W2 @ Wp, 8 rows/block, k-unroll 8 ----------------
        int d0 = (br - 2 * BB) * 8, e = tid;
        float* w2s = fpool;   // 8*256
        for (int i = tid; i < 8 * DD; i += 256) w2s[i] = W2[d0 * DD + i];
        __syncthreads();
        float a[8];
#pragma unroll
        for (int r = 0; r < 8; r++) a[r] = 0.f;
        for (int k = 0; k < DD; k += 8) {
            float wp[8];
#pragma unroll
            for (int j = 0; j < 8; j++) wp[j] = Wp[(k + j) * DD + e];
#pragma unroll
            for (int j = 0; j < 8; j++)
#pragma unroll
                for (int r = 0; r < 8; r++) a[r] += w2s[r * DD + k + j] * wp[j];
        }
#pragma unroll
        for (int r = 0; r < 8; r++) g_E[(d0 + r) * DD + e] = a[r];
    } else if (br == 2 * BB + 32) {
        // ---------------- r = b2 @ Wp ----------------
        float a = 0.f;
#pragma unroll 8
        for (int k = 0; k < DD; k++) a += b2[k] * Wp[k * DD + tid];
        g_r[tid] = a;
    } else {
        // ---------------- pad W1 (261x256) -> g_W1p (288x256) ----------------
        int i = (br - (2 * BB + 33)) * 256 + tid;   // float4 idx 0..18431
        const float4* w14 = (const float4*)W1;      // 16704 real float4s
        float4 v = make_float4(0.f, 0.f, 0.f, 0.f);
        if (i < 16704) v = w14[i];
        ((float4*)g_W1p)[i] = v;
    }
}
#define PRE_GRID (2 * BB + 33 + 72)   // 361

// =========================================================================
// MLP kernel — EXACT round-4 version (measured 32.5-32.8us, FFMA floor).
// =========================================================================
__global__ __launch_bounds__(256) void mlp_kernel(const float* __restrict__ b1,
                                                  const float* __restrict__ gamma,
                                                  const float* __restrict__ beta,
                                                  const float* __restrict__ bp,
                                                  const float* __restrict__ osp,
                                                  float* __restrict__ out) {
    int b = blockIdx.x, tid = threadIdx.x;
    int rg = tid >> 6, cg = tid & 63;
    int r0 = rg * 4, e0 = cg * 4;
    int wid = tid >> 5, lane = tid & 31;

    extern __shared__ float sm[];
    float* csT  = sm;               // 288*16 = 4608
    float* wb0  = csT + 4608;       // 32*256 = 8192
    float* wb1  = wb0 + 8192;       // 8192
    float* hsT  = wb1 + 8192;       // 256*16 = 4096
    float* red  = hsT + 4096;       // 32
    float* red2 = red + 32;         // 32
    float* u_s  = red2 + 32;        // 256
    float* q_s  = u_s + 256;        // 256
    __shared__ float dots[MAXO], mur[MAXO], rstdr[MAXO];
    __shared__ int vld[MAXO];

    const float4* cb4 = (const float4*)(g_comb + (size_t)b * FPITCH * MAXO);
    for (int i = tid; i < (FPITCH * MAXO) / 4; i += 256)
        ((float4*)csT)[i] = cb4[i];
    u_s[tid] = g_u[b * DD + tid];
    q_s[tid] = g_q[b * DD + tid];
    if (tid < MAXO) vld[tid] = g_valid[b * MAXO + tid];

    const float4* w14 = (const float4*)g_W1p;
    const float4* e4  = (const float4*)g_E;

    {
        float4 pf[8];
#pragma unroll
        for (int j = 0; j < 8; j++) pf[j] = w14[tid + j * 256];
#pragma unroll
        for (int j = 0; j < 8; j++) ((float4*)wb0)[tid + j * 256] = pf[j];
    }
    __syncthreads();

    float bdot = g_bdot[b];
    float os = osp[0];

    float acc[4][4];
#pragma unroll
    for (int i = 0; i < 4; i++)
#pragma unroll
        for (int j = 0; j < 4; j++) acc[i][j] = 0.f;

    for (int t = 0; t < 9; t++) {
        float4 pf[8];
        if (t < 8) {
            int base = (t + 1) * 2048;
#pragma unroll
            for (int j = 0; j < 8; j++) pf[j] = w14[base + tid + j * 256];
        }
        const float* wcur = (t & 1) ? wb1 : wb0;
#pragma unroll
        for (int kk = 0; kk < 32; kk++) {
            float4 c4 = *(const float4*)&csT[(t * 32 + kk) * MAXO + r0];
            float4 w4 = *(const float4*)&wcur[kk * 256 + e0];
            float ca[4] = {c4.x, c4.y, c4.z, c4.w};
            float wa[4] = {w4.x, w4.y, w4.z, w4.w};
#pragma unroll
            for (int i = 0; i < 4; i++)
#pragma unroll
                for (int j = 0; j < 4; j++) acc[i][j] += ca[i] * wa[j];
        }
        __syncthreads();
        if (t < 8) {
            float* wn = (t & 1) ? wb0 : wb1;
#pragma unroll
            for (int j = 0; j < 8; j++) ((float4*)wn)[tid + j * 256] = pf[j];
            __syncthreads();
        }
    }

    float4 b14 = *(const float4*)&b1[e0];
    float bb[4] = {b14.x, b14.y, b14.z, b14.w};
    float h[4][4];
#pragma unroll
    for (int i = 0; i < 4; i++)
#pragma unroll
        for (int j = 0; j < 4; j++) {
            float xx = acc[i][j] + bb[j];
            h[i][j] = 0.5f * xx * (1.0f + erff(xx * 0.70710678118654752f));
        }
#pragma unroll
    for (int j = 0; j < 4; j++) {
        float4 v = make_float4(h[0][j], h[1][j], h[2][j], h[3][j]);
        *(float4*)&hsT[(e0 + j) * MAXO + r0] = v;
    }

    float uu[4] = {u_s[e0], u_s[e0 + 1], u_s[e0 + 2], u_s[e0 + 3]};
    float p[4];
#pragma unroll
    for (int i = 0; i < 4; i++)
        p[i] = h[i][0] * uu[0] + h[i][1] * uu[1] + h[i][2] * uu[2] + h[i][3] * uu[3];
#pragma unroll
    for (int off = 16; off; off >>= 1)
#pragma unroll
        for (int i = 0; i < 4; i++) p[i] += __shfl_down_sync(0xffffffffu, p[i], off);
    if (lane == 0) {
#pragma unroll
        for (int i = 0; i < 4; i++) red[(r0 + i) * 2 + (wid & 1)] = p[i];
    }
    __syncthreads();
    if (tid < MAXO) dots[tid] = red[tid * 2] + red[tid * 2 + 1] + bdot;

    {
        float4 pf[8];
#pragma unroll
        for (int j = 0; j < 8; j++) pf[j] = e4[tid + j * 256];
#pragma unroll
        for (int j = 0; j < 8; j++) ((float4*)wb0)[tid + j * 256] = pf[j];
    }
    __syncthreads();

    float a2[4][4];
#pragma unroll
    for (int i = 0; i < 4; i++)
#pragma unroll
        for (int j = 0; j < 4; j++) a2[i][j] = 0.f;

    for (int t = 0; t < 8; t++) {
        float4 pf[8];
        if (t < 7) {
            int base = (t + 1) * 2048;
#pragma unroll
            for (int j = 0; j < 8; j++) pf[j] = e4[base + tid + j * 256];
        }
        const float* wcur = (t & 1) ? wb1 : wb0;
#pragma unroll
        for (int kk = 0; kk < 32; kk++) {
            float4 h4 = *(const float4*)&hsT[(t * 32 + kk) * MAXO + r0];
            float4 w4 = *(const float4*)&wcur[kk * 256 + e0];
            float ha[4] = {h4.x, h4.y, h4.z, h4.w};
            float wa[4] = {w4.x, w4.y, w4.z, w4.w};
#pragma unroll
            for (int i = 0; i < 4; i++)
#pragma unroll
                for (int j = 0; j < 4; j++) a2[i][j] += ha[i] * wa[j];
        }
        __syncthreads();
        if (t < 7) {
            float* wn = (t & 1) ? wb0 : wb1;
#pragma unroll
            for (int j = 0; j < 8; j++) ((float4*)wn)[tid + j * 256] = pf[j];
            __syncthreads();
        }
    }

    float4 bp4 = *(const float4*)&bp[e0];
    float4 rv4 = *(const float4*)&g_r[e0];
    float bpp[4] = {bp4.x, bp4.y, bp4.z, bp4.w};
    float rr[4] = {rv4.x, rv4.y, rv4.z, rv4.w};
    float qq[4] = {q_s[e0], q_s[e0 + 1], q_s[e0 + 2], q_s[e0 + 3]};
    float pre[4][4];
#pragma unroll
    for (int i = 0; i < 4; i++) {
        float dt = dots[r0 + i];
        int v = vld[r0 + i];
#pragma unroll
        for (int j = 0; j < 4; j++) {
            float pv = os * (a2[i][j] + rr[j] - dt * qq[j]) + bpp[j];
            pre[i][j] = v ? pv : bpp[j];
        }
    }

    float ps[4], pq[4];
#pragma unroll
    for (int i = 0; i < 4; i++) {
        ps[i] = pre[i][0] + pre[i][1] + pre[i][2] + pre[i][3];
        pq[i] = pre[i][0] * pre[i][0] + pre[i][1] * pre[i][1] +
                pre[i][2] * pre[i][2] + pre[i][3] * pre[i][3];
    }
#pragma unroll
    for (int off = 16; off; off >>= 1)
#pragma unroll
        for (int i = 0; i < 4; i++) {
            ps[i] += __shfl_down_sync(0xffffffffu, ps[i], off);
            pq[i] += __shfl_down_sync(0xffffffffu, pq[i], off);
        }
    if (lane == 0) {
#pragma unroll
        for (int i = 0; i < 4; i++) {
            red[(r0 + i) * 2 + (wid & 1)] = ps[i];
            red2[(r0 + i) * 2 + (wid & 1)] = pq[i];
        }
    }
    __syncthreads();
    if (tid < MAXO) {
        float m = (red[tid * 2] + red[tid * 2 + 1]) * (1.0f / DD);
        mur[tid] = m;
        float va = (red2[tid * 2] + red2[tid * 2 + 1]) * (1.0f / DD) - m * m;
        rstdr[tid] = rsqrtf(va + 1e-5f);
    }
    __syncthreads();

    float4 g4 = *(const float4*)&gamma[e0];
    float4 be4 = *(const float4*)&beta[e0];
    float gg[4] = {g4.x, g4.y, g4.z, g4.w};
    float bee[4] = {be4.x, be4.y, be4.z, be4.w};
#pragma unroll
    for (int i = 0; i < 4; i++) {
        float m = mur[r0 + i], rs = rstdr[r0 + i];
        float4 o;
        o.x = (pre[i][0] - m) * rs * gg[0] + bee[0];
        o.y = (pre[i][1] - m) * rs * gg[1] + bee[1];
        o.z = (pre[i][2] - m) * rs * gg[2] + bee[2];
        o.w = (pre[i][3] - m) * rs * gg[3] + bee[3];
        *(float4*)&out[((size_t)(b * MAXO + r0 + i)) * DD + e0] = o;
    }
}

#define MLP_SMEM ((4608 + 8192 + 8192 + 4096 + 32 + 32 + 256 + 256) * 4)

// =========================================================================
extern "C" void kernel_launch(void* const* d_in, const int* in_sizes, int n_in,
                              void* d_out, int out_size) {
    const float* grid_emb = (const float*)d_in[0];
    const int*   grid     = (const int*)d_in[1];
    const float* sr       = (const float*)d_in[2];
    const float* W1       = (const float*)d_in[3];
    const float* b1       = (const float*)d_in[4];
    const float* W2       = (const float*)d_in[5];
    const float* b2       = (const float*)d_in[6];
    const float* Wp       = (const float*)d_in[7];
    const float* bp       = (const float*)d_in[8];
    const float* gamma    = (const float*)d_in[9];
    const float* beta     = (const float*)d_in[10];
    const float* os       = (const float*)d_in[11];

    cudaFuncSetAttribute(mlp_kernel, cudaFuncAttributeMaxDynamicSharedMemorySize, MLP_SMEM);

    pre_kernel<<<PRE_GRID, 256>>>(grid_emb, grid, sr, W1, W2, Wp, b2);
    mlp_kernel<<<BB, 256, MLP_SMEM>>>(b1, gamma, beta, bp, os, (float*)d_out);
}

// round 9
// speedup vs baseline: 1.0999x; 1.0059x over previous
#include <cuda_runtime.h>
#include <math.h>

#define HH 30
#define WWG 30
#define HW 900
#define DD 256
#define MAXO 16
#define BB 128
#define FPITCH 288   // 261 feature rows padded to 288 (9 K-tiles of 32)
#define CHUNK 1024
#define PF 8         // pooling prefetch depth (per group)

// ---------------- device scratch ----------------
__device__ __align__(16) float g_comb[BB * FPITCH * MAXO];  // [b][feat][k]
__device__ __align__(16) float g_u[BB * DD];
__device__ __align__(16) float g_q[BB * DD];
__device__ float g_bdot[BB];
__device__ __align__(16) float g_E[DD * DD];                // W2 @ Wp
__device__ __align__(16) float g_r[DD];                     // b2 @ Wp
__device__ __align__(16) float g_W1p[FPITCH * DD];          // W1 padded
__device__ int   g_valid[BB * MAXO];

// =========================================================================
// Fused pre-kernel, 1024 threads/block.
// blockIdx: [0,128) ccl+features, [128,256) prep, [256,288) E (8 rows),
// 288 r, [289,307) W1 pad copy.
// =========================================================================
__global__ __launch_bounds__(1024) void pre_kernel(const float* __restrict__ grid_emb,
                                                   const int* __restrict__ grid,
                                                   const float* __restrict__ sr,
                                                   const float* __restrict__ W1,
                                                   const float* __restrict__ W2,
                                                   const float* __restrict__ Wp,
                                                   const float* __restrict__ b2) {
    int br = blockIdx.x, tid = threadIdx.x;

    __shared__ __align__(16) char spool[46080];
    __shared__ unsigned rootbits[32];
    __shared__ int wpre[32];
    __shared__ int s_flag[2];
    __shared__ int nvalid;
    __shared__ int robj[MAXO], rmin[MAXO], rmax[MAXO], cmin[MAXO], cmax[MAXO];
    __shared__ int offs[MAXO + 1];

    if (br < BB) {
        // ---------------- CCL + features ----------------
        int* g       = (int*)spool;                    // 3600 B
        int* lab     = g + HW;                         // 3600 B
        int* slot_of = lab + HW;                       // 3600 B (ends 10800)
        float* fpool = (float*)(spool + 10816);        // 16 KB (ends 27200)
        int* ipool   = (int*)(spool + 27200);          // 4 KB

        int b = br;
        for (int c = tid; c < HW; c += 1024) {
            int v = grid[b * HW + c];
            g[c] = v;
            lab[c] = (v > 0) ? c : HW;
            slot_of[c] = -1;
        }
        if (tid < 32) rootbits[tid] = 0;
        if (tid == 0) { s_flag[0] = 0; s_flag[1] = 0; }
        __syncthreads();

        for (int it = 0; it < 512; it++) {
            int f = it & 1;
            if (tid == 0) s_flag[1 - f] = 0;
            int changed = 0;
            for (int c = tid; c < HW; c += 1024) {
                int gc = g[c];
                if (gc > 0) {
                    int m = lab[c];
                    int col = c % WWG;
                    if (c >= WWG && g[c - WWG] == gc) { int t = lab[c - WWG]; if (t < m) m = t; }
                    if (c < HW - WWG && g[c + WWG] == gc) { int t = lab[c + WWG]; if (t < m) m = t; }
                    if (col > 0 && g[c - 1] == gc) { int t = lab[c - 1]; if (t < m) m = t; }
                    if (col < WWG - 1 && g[c + 1] == gc) { int t = lab[c + 1]; if (t < m) m = t; }
#pragma unroll
                    for (int hop = 0; hop < 8; hop++) {
                        int p = lab[m];
                        if (p >= m) break;
                        m = p;
                    }
                    if (m < lab[c]) { lab[c] = m; changed = 1; }
                }
            }
            if (changed) s_flag[f] = 1;
            __syncthreads();
            int ch = s_flag[f];
            __syncthreads();
            if (!ch) break;
        }

        for (int c = tid; c < HW; c += 1024)
            if (g[c] > 0 && lab[c] == c) atomicOr(&rootbits[c >> 5], 1u << (c & 31));
        __syncthreads();
        if (tid == 0) {
            int s = 0;
            for (int w = 0; w < 29; w++) { wpre[w] = s; s += __popc(rootbits[w]); }
            nvalid = s < MAXO ? s : MAXO;
        }
        __syncthreads();
        for (int c = tid; c < HW; c += 1024) {
            if (g[c] > 0 && lab[c] == c) {
                int w = c >> 5;
                int rank = wpre[w] + __popc(rootbits[w] & ((1u << (c & 31)) - 1u));
                if (rank < MAXO) { robj[rank] = c; slot_of[c] = rank; }
            }
        }
        if (tid < MAXO) { rmin[tid] = HH; rmax[tid] = -1; cmin[tid] = WWG; cmax[tid] = -1; }
        __syncthreads();
        for (int c = tid; c < HW; c += 1024) {
            if (g[c] > 0) {
                int s = slot_of[lab[c]];
                if (s >= 0) {
                    int r = c / WWG, col = c % WWG;
                    atomicMin(&rmin[s], r); atomicMax(&rmax[s], r);
                    atomicMin(&cmin[s], col); atomicMax(&cmax[s], col);
                }
            }
        }
        __syncthreads();

        int nv = nvalid;
        if (tid == 0) {
            int off = 0;
            for (int k = 0; k < nv; k++) {
                offs[k] = off;
                off += (rmax[k] + 1 - rmin[k]) * (cmax[k] + 1 - cmin[k]);
            }
            offs[nv] = off;
        }
        for (int i = tid; i < MAXO * DD; i += 1024) fpool[i] = 0.f;
        __syncthreads();

        int total = offs[nv];
        int ch = tid & 255, grp = tid >> 8;    // 4 entry-groups x 256 channels
        const float* gbase = grid_emb + (size_t)b * HW * DD + ch;
        for (int base = 0; base < total; base += CHUNK) {
            int n = min(CHUNK, total - base);
            for (int e = tid; e < n; e += 1024) {
                int ge = base + e;
                int k = 0;
                while (k + 1 < nv && ge >= offs[k + 1]) k++;
                int local = ge - offs[k];
                int bw = cmax[k] + 1 - cmin[k];
                int li = local / bw, lj = local - li * bw;
                int cell = (rmin[k] + li) * WWG + cmin[k] + lj;
                ipool[e] = (k << 16) | cell;
            }
            __syncthreads();
            int n4 = (n + 3) >> 2;
            int s0 = grp * n4, s1 = min(n, s0 + n4);
            float run = 0.f;
            int prev = -1;
            for (int e0b = s0; e0b < s1; e0b += PF) {
                int m = s1 - e0b; if (m > PF) m = PF;
                float v[PF]; int kk[PF];
#pragma unroll
                for (int j = 0; j < PF; j++) {
                    if (j < m) {
                        int ent = ipool[e0b + j];
                        kk[j] = ent >> 16;
                        v[j] = gbase[(size_t)(ent & 0xffff) * DD];
                    }
                }
#pragma unroll
                for (int j = 0; j < PF; j++) {
                    if (j < m) {
                        if (kk[j] != prev) {
                            if (prev >= 0) atomicAdd(&fpool[prev * DD + ch], run);
                            run = 0.f;
                            prev = kk[j];
                        }
                        run += v[j];
                    }
                }
            }
            if (prev >= 0) atomicAdd(&fpool[prev * DD + ch], run);
            __syncthreads();
        }

        float* cb = g_comb + (size_t)b * FPITCH * MAXO;
        for (int i = tid; i < FPITCH * MAXO; i += 1024) cb[i] = 0.f;
        if (tid < MAXO) g_valid[b * MAXO + tid] = (tid < nv) ? 1 : 0;
        __syncthreads();
        if (tid < DD) {
            for (int k = 0; k < nv; k++) {
                int y = rmin[k], x = cmin[k];
                int h = rmax[k] + 1 - y, w = cmax[k] + 1 - x;
                cb[tid * MAXO + k] = fpool[k * DD + tid] / (float)(h * w);
                if (tid < 5) {
                    float v;
                    int color = g[robj[k]];
                    if (tid == 0)      v = (float)color * (1.0f / 9.0f);
                    else if (tid == 1) v = (float)x * (1.0f / WWG);
                    else if (tid == 2) v = (float)y * (1.0f / HH);
                    else if (tid == 3) v = (float)w * (1.0f / WWG);
                    else               v = (float)h * (1.0f / HH);
                    cb[(DD + tid) * MAXO + k] = v;
                }
            }
        }
    } else if (br < 2 * BB) {
        // ---------------- prep: sn, u, q, bdot ----------------
        int b = br - BB;
        float* sn   = (float*)spool;
        float* sred = sn + DD;
        float s = 0.f;
        if (tid < DD) {
            const float* base = sr + (size_t)b * 8 * DD + tid;
#pragma unroll
            for (int j = 0; j < 8; j++) s += base[j * DD];
            s *= 0.125f;
            sred[tid] = s * s;
        }
        __syncthreads();
        for (int off = 128; off; off >>= 1) {
            if (tid < off) sred[tid] += sred[tid + off];
            __syncthreads();
        }
        float nrm = sqrtf(sred[0]);
        __syncthreads();
        float snv = s / fmaxf(nrm, 1e-8f);
        if (tid < DD) { sn[tid] = snv; sred[tid] = snv * b2[tid]; }
        __syncthreads();
        for (int off = 128; off; off >>= 1) {
            if (tid < off) sred[tid] += sred[tid + off];
            __syncthreads();
        }
        if (tid == 0) g_bdot[b] = sred[0];

        if (tid < DD) {
            float acc = 0.f;
#pragma unroll 8
            for (int d = 0; d < DD; d++) acc += sn[d] * Wp[d * DD + tid];
            g_q[b * DD + tid] = acc;
        }

        int wid = tid >> 5, lane = tid & 31;
        for (int d = wid; d < DD; d += 32) {
            float a = 0.f;
            const float* wr = W2 + d * DD;
#pragma unroll 4
            for (int e2 = lane; e2 < DD; e2 += 32) a += wr[e2] * sn[e2];
#pragma unroll
            for (int off = 16; off; off >>= 1) a += __shfl_down_sync(0xffffffffu, a, off);
            if (lane == 0) g_u[b * DD + d] = a;
        }
    } else if (br < 2 * BB + 32) {
        // ---------------- E = W2 @ Wp: 8 rows/block, Wp smem-tiled ----------------
        int d0 = (br - 2 * BB) * 8;
        int e = tid & 255, sub = tid >> 8;     // 4 subs x 2 rows
        int r0 = sub * 2;
        float* wpt = (float*)spool;            // 32x256 = 32 KB
        float* w2s = (float*)(spool + 32768);  // 8x256 = 8 KB
        for (int i = tid; i < 8 * DD; i += 1024) w2s[i] = W2[d0 * DD + i];
        const float4* wp4 = (const float4*)Wp; // 16384 float4 (8 tiles of 2048)
        float4 pf0 = wp4[tid], pf1 = wp4[tid + 1024];
        __syncthreads();
        float a0 = 0.f, a1 = 0.f;
        for (int t = 0; t < 8; t++) {
            ((float4*)wpt)[tid] = pf0;
            ((float4*)wpt)[tid + 1024] = pf1;
            __syncthreads();
            if (t < 7) {
                pf0 = wp4[(t + 1) * 2048 + tid];
                pf1 = wp4[(t + 1) * 2048 + tid + 1024];
            }
#pragma unroll 8
            for (int k = 0; k < 32; k++) {
                float wp = wpt[k * 256 + e];
                a0 += w2s[r0 * DD + t * 32 + k] * wp;
                a1 += w2s[(r0 + 1) * DD + t * 32 + k] * wp;
            }
            __syncthreads();
        }
        g_E[(d0 + r0) * DD + e] = a0;
        g_E[(d0 + r0 + 1) * DD + e] = a1;
    } else if (br == 2 * BB + 32) {
        // ---------------- r = b2 @ Wp ----------------
        if (tid < DD) {
            float a = 0.f;
#pragma unroll 8
            for (int k = 0; k < DD; k++) a += b2[k] * Wp[k * DD + tid];
            g_r[tid] = a;
        }
    } else {
        // ---------------- pad W1 (261x256) -> g_W1p (288x256) ----------------
        int i = (br - (2 * BB + 33)) * 1024 + tid;  // float4 idx 0..18431
        if (i < FPITCH * DD / 4) {
            const float4* w14 = (const float4*)W1;  // 16704 real float4s
            float4 v = make_float4(0.f, 0.f, 0.f, 0.f);
            if (i < 16704) v = w14[i];
            ((float4*)g_W1p)[i] = v;
        }
    }
}
#define PRE_GRID (2 * BB + 33 + 18)   // 307

// =========================================================================
// MLP kernel — EXACT round-4 version (measured 32.5-34us, FFMA floor).
// =========================================================================
__global__ __launch_bounds__(256) void mlp_kernel(const float* __restrict__ b1,
                                                  const float* __restrict__ gamma,
                                                  const float* __restrict__ beta,
                                                  const float* __restrict__ bp,
                                                  const float* __restrict__ osp,
                                                  float* __restrict__ out) {
    int b = blockIdx.x, tid = threadIdx.x;
    int rg = tid >> 6, cg = tid & 63;
    int r0 = rg * 4, e0 = cg * 4;
    int wid = tid >> 5, lane = tid & 31;

    extern __shared__ float sm[];
    float* csT  = sm;               // 288*16 = 4608
    float* wb0  = csT + 4608;       // 32*256 = 8192
    float* wb1  = wb0 + 8192;       // 8192
    float* hsT  = wb1 + 8192;       // 256*16 = 4096
    float* red  = hsT + 4096;       // 32
    float* red2 = red + 32;         // 32
    float* u_s  = red2 + 32;        // 256
    float* q_s  = u_s + 256;        // 256
    __shared__ float dots[MAXO], mur[MAXO], rstdr[MAXO];
    __shared__ int vld[MAXO];

    const float4* cb4 = (const float4*)(g_comb + (size_t)b * FPITCH * MAXO);
    for (int i = tid; i < (FPITCH * MAXO) / 4; i += 256)
        ((float4*)csT)[i] = cb4[i];
    u_s[tid] = g_u[b * DD + tid];
    q_s[tid] = g_q[b * DD + tid];
    if (tid < MAXO) vld[tid] = g_valid[b * MAXO + tid];

    const float4* w14 = (const float4*)g_W1p;
    const float4* e4  = (const float4*)g_E;

    {
        float4 pf[8];
#pragma unroll
        for (int j = 0; j < 8; j++) pf[j] = w14[tid + j * 256];
#pragma unroll
        for (int j = 0; j < 8; j++) ((float4*)wb0)[tid + j * 256] = pf[j];
    }
    __syncthreads();

    float bdot = g_bdot[b];
    float os = osp[0];

    float acc[4][4];
#pragma unroll
    for (int i = 0; i < 4; i++)
#pragma unroll
        for (int j = 0; j < 4; j++) acc[i][j] = 0.f;

    for (int t = 0; t < 9; t++) {
        float4 pf[8];
        if (t < 8) {
            int base = (t + 1) * 2048;
#pragma unroll
            for (int j = 0; j < 8; j++) pf[j] = w14[base + tid + j * 256];
        }
        const float* wcur = (t & 1) ? wb1 : wb0;
#pragma unroll
        for (int kk = 0; kk < 32; kk++) {
            float4 c4 = *(const float4*)&csT[(t * 32 + kk) * MAXO + r0];
            float4 w4 = *(const float4*)&wcur[kk * 256 + e0];
            float ca[4] = {c4.x, c4.y, c4.z, c4.w};
            float wa[4] = {w4.x, w4.y, w4.z, w4.w};
#pragma unroll
            for (int i = 0; i < 4; i++)
#pragma unroll
                for (int j = 0; j < 4; j++) acc[i][j] += ca[i] * wa[j];
        }
        __syncthreads();
        if (t < 8) {
            float* wn = (t & 1) ? wb0 : wb1;
#pragma unroll
            for (int j = 0; j < 8; j++) ((float4*)wn)[tid + j * 256] = pf[j];
            __syncthreads();
        }
    }

    float4 b14 = *(const float4*)&b1[e0];
    float bb[4] = {b14.x, b14.y, b14.z, b14.w};
    float h[4][4];
#pragma unroll
    for (int i = 0; i < 4; i++)
#pragma unroll
        for (int j = 0; j < 4; j++) {
            float xx = acc[i][j] + bb[j];
            h[i][j] = 0.5f * xx * (1.0f + erff(xx * 0.70710678118654752f));
        }
#pragma unroll
    for (int j = 0; j < 4; j++) {
        float4 v = make_float4(h[0][j], h[1][j], h[2][j], h[3][j]);
        *(float4*)&hsT[(e0 + j) * MAXO + r0] = v;
    }

    float uu[4] = {u_s[e0], u_s[e0 + 1], u_s[e0 + 2], u_s[e0 + 3]};
    float p[4];
#pragma unroll
    for (int i = 0; i < 4; i++)
        p[i] = h[i][0] * uu[0] + h[i][1] * uu[1] + h[i][2] * uu[2] + h[i][3] * uu[3];
#pragma unroll
    for (int off = 16; off; off >>= 1)
#pragma unroll
        for (int i = 0; i < 4; i++) p[i] += __shfl_down_sync(0xffffffffu, p[i], off);
    if (lane == 0) {
#pragma unroll
        for (int i = 0; i < 4; i++) red[(r0 + i) * 2 + (wid & 1)] = p[i];
    }
    __syncthreads();
    if (tid < MAXO) dots[tid] = red[tid * 2] + red[tid * 2 + 1] + bdot;

    {
        float4 pf[8];
#pragma unroll
        for (int j = 0; j < 8; j++) pf[j] = e4[tid + j * 256];
#pragma unroll
        for (int j = 0; j < 8; j++) ((float4*)wb0)[tid + j * 256] = pf[j];
    }
    __syncthreads();

    float a2[4][4];
#pragma unroll
    for (int i = 0; i < 4; i++)
#pragma unroll
        for (int j = 0; j < 4; j++) a2[i][j] = 0.f;

    for (int t = 0; t < 8; t++) {
        float4 pf[8];
        if (t < 7) {
            int base = (t + 1) * 2048;
#pragma unroll
            for (int j = 0; j < 8; j++) pf[j] = e4[base + tid + j * 256];
        }
        const float* wcur = (t & 1) ? wb1 : wb0;
#pragma unroll
        for (int kk = 0; kk < 32; kk++) {
            float4 h4 = *(const float4*)&hsT[(t * 32 + kk) * MAXO + r0];
            float4 w4 = *(const float4*)&wcur[kk * 256 + e0];
            float ha[4] = {h4.x, h4.y, h4.z, h4.w};
            float wa[4] = {w4.x, w4.y, w4.z, w4.w};
#pragma unroll
            for (int i = 0; i < 4; i++)
#pragma unroll
                for (int j = 0; j < 4; j++) a2[i][j] += ha[i] * wa[j];
        }
        __syncthreads();
        if (t < 7) {
            float* wn = (t & 1) ? wb0 : wb1;
#pragma unroll
            for (int j = 0; j < 8; j++) ((float4*)wn)[tid + j * 256] = pf[j];
            __syncthreads();
        }
    }

    float4 bp4 = *(const float4*)&bp[e0];
    float4 rv4 = *(const float4*)&g_r[e0];
    float bpp[4] = {bp4.x, bp4.y, bp4.z, bp4.w};
    float rr[4] = {rv4.x, rv4.y, rv4.z, rv4.w};
    float qq[4] = {q_s[e0], q_s[e0 + 1], q_s[e0 + 2], q_s[e0 + 3]};
    float pre[4][4];
#pragma unroll
    for (int i = 0; i < 4; i++) {
        float dt = dots[r0 + i];
        int v = vld[r0 + i];
#pragma unroll
        for (int j = 0; j < 4; j++) {
            float pv = os * (a2[i][j] + rr[j] - dt * qq[j]) + bpp[j];
            pre[i][j] = v ? pv : bpp[j];
        }
    }

    float ps[4], pq[4];
#pragma unroll
    for (int i = 0; i < 4; i++) {
        ps[i] = pre[i][0] + pre[i][1] + pre[i][2] + pre[i][3];
        pq[i] = pre[i][0] * pre[i][0] + pre[i][1] * pre[i][1] +
                pre[i][2] * pre[i][2] + pre[i][3] * pre[i][3];
    }
#pragma unroll
    for (int off = 16; off; off >>= 1)
#pragma unroll
        for (int i = 0; i < 4; i++) {
            ps[i] += __shfl_down_sync(0xffffffffu, ps[i], off);
            pq[i] += __shfl_down_sync(0xffffffffu, pq[i], off);
        }
    if (lane == 0) {
#pragma unroll
        for (int i = 0; i < 4; i++) {
            red[(r0 + i) * 2 + (wid & 1)] = ps[i];
            red2[(r0 + i) * 2 + (wid & 1)] = pq[i];
        }
    }
    __syncthreads();
    if (tid < MAXO) {
        float m = (red[tid * 2] + red[tid * 2 + 1]) * (1.0f / DD);
        mur[tid] = m;
        float va = (red2[tid * 2] + red2[tid * 2 + 1]) * (1.0f / DD) - m * m;
        rstdr[tid] = rsqrtf(va + 1e-5f);
    }
    __syncthreads();

    float4 g4 = *(const float4*)&gamma[e0];
    float4 be4 = *(const float4*)&beta[e0];
    float gg[4] = {g4.x, g4.y, g4.z, g4.w};
    float bee[4] = {be4.x, be4.y, be4.z, be4.w};
#pragma unroll
    for (int i = 0; i < 4; i++) {
        float m = mur[r0 + i], rs = rstdr[r0 + i];
        float4 o;
        o.x = (pre[i][0] - m) * rs * gg[0] + bee[0];
        o.y = (pre[i][1] - m) * rs * gg[1] + bee[1];
        o.z = (pre[i][2] - m) * rs * gg[2] + bee[2];
        o.w = (pre[i][3] - m) * rs * gg[3] + bee[3];
        *(float4*)&out[((size_t)(b * MAXO + r0 + i)) * DD + e0] = o;
    }
}

#define MLP_SMEM ((4608 + 8192 + 8192 + 4096 + 32 + 32 + 256 + 256) * 4)

// =========================================================================
extern "C" void kernel_launch(void* const* d_in, const int* in_sizes, int n_in,
                              void* d_out, int out_size) {
    const float* grid_emb = (const float*)d_in[0];
    const int*   grid     = (const int*)d_in[1];
    const float* sr       = (const float*)d_in[2];
    const float* W1       = (const float*)d_in[3];
    const float* b1       = (const float*)d_in[4];
    const float* W2       = (const float*)d_in[5];
    const float* b2       = (const float*)d_in[6];
    const float* Wp       = (const float*)d_in[7];
    const float* bp       = (const float*)d_in[8];
    const float* gamma    = (const float*)d_in[9];
    const float* beta     = (const float*)d_in[10];
    const float* os       = (const float*)d_in[11];

    cudaFuncSetAttribute(mlp_kernel, cudaFuncAttributeMaxDynamicSharedMemorySize, MLP_SMEM);

    pre_kernel<<<PRE_GRID, 1024>>>(grid_emb, grid, sr, W1, W2, Wp, b2);
    mlp_kernel<<<BB, 256, MLP_SMEM>>>(b1, gamma, beta, bp, os, (float*)d_out);
}